// round 10
// baseline (speedup 1.0000x reference)
#include <cuda_runtime.h>

// BoidPolicy: all-pairs boids on a unit torus, N=8192, out acc [N,2] f32.
//
// Pipeline (graph-capturable, allocation-free, 2 launches):
//  kS: fused spatial sort (1 block x 1024 thr): 16x16 snake cells -> smem histogram
//      ranks -> scan -> scatter into interleaved pos/vel pair records + cell bytes
//  k1: TWO blocks per 32-i tile (512 thr): cull cells vs tile bbox (perc AND sep
//      radii) -> two compacted pair lists -> main loop (perception only, packed
//      f32x2, unroll-4, packed index loads) + tiny separation loop ->
//      reduce -> ticketed fused epilogue.

#define NB      8192
#define NCELL   256
#define NTILE   256
#define TPB1    512
#define NWARP   16            // warps per block
#define NSEG    32            // segments per tile (2 blocks x 16 warps)

#define SEP2F   4e-4f
#define PERC2F  0.04f
#define EPSF    1e-8f
#define MAGIC   12582912.0f   // 1.5 * 2^23
#define FULLM   0xffffffffu

typedef unsigned long long u64;
typedef unsigned short u16;

__device__ float4 g_pv[NB];             // pair p: g_pv[2p]=(xA,xB,yA,yB), g_pv[2p+1]=(vxA,vxB,vyA,vyB)
__device__ int    g_orig[NB];
__device__ uint4  g_scellv[NB / 16];    // sorted cell ids, 1 byte per boid
__device__ float  g_part[2][7][NB];     // [parity][comp][sorted boid]
__device__ int    g_ticket[NTILE];

__device__ __forceinline__ u64 pack2(float lo, float hi) {
    u64 r; asm("mov.b64 %0,{%1,%2};" : "=l"(r) : "f"(lo), "f"(hi)); return r;
}
__device__ __forceinline__ void unpack2(u64 v, float& lo, float& hi) {
    asm("mov.b64 {%0,%1},%2;" : "=f"(lo), "=f"(hi) : "l"(v));
}
__device__ __forceinline__ u64 f2add(u64 a, u64 b) {
    u64 d; asm("add.rn.f32x2 %0,%1,%2;" : "=l"(d) : "l"(a), "l"(b)); return d;
}
__device__ __forceinline__ u64 f2mul(u64 a, u64 b) {
    u64 d; asm("mul.rn.f32x2 %0,%1,%2;" : "=l"(d) : "l"(a), "l"(b)); return d;
}
__device__ __forceinline__ u64 f2fma(u64 a, u64 b, u64 c) {
    u64 d; asm("fma.rn.f32x2 %0,%1,%2,%3;" : "=l"(d) : "l"(a), "l"(b), "l"(c)); return d;
}
// per-half: (t >= 0) ? 1.0f : 0.0f  (exact: copysign(0.5,t)+0.5)
__device__ __forceinline__ u64 f2mask(u64 t, u64 half2) {
    u64 s = (t & 0x8000000080000000ULL) | 0x3F0000003F000000ULL;
    return f2add(s, half2);
}
__device__ __forceinline__ float wrap1(float d) { return d - rintf(d); }
__device__ __forceinline__ float getX(const float* P, int idx) {
    return P[(idx >> 1) * 8 + (idx & 1)];
}
__device__ __forceinline__ float getY(const float* P, int idx) {
    return P[(idx >> 1) * 8 + 2 + (idx & 1)];
}

// ---------------- kS: fused sort (one block, 1024 threads, 8 boids each) ----------------
__global__ __launch_bounds__(1024)
void kS_sort(const float2* __restrict__ pos, const float2* __restrict__ vel)
{
    __shared__ int hist[NCELL];
    __shared__ int soff[NCELL];
    __shared__ int wsum[8];
    __shared__ int wbase[8];

    const int tid  = threadIdx.x;
    const int lane = tid & 31;
    const int w    = tid >> 5;

    if (tid < NCELL) { hist[tid] = 0; g_ticket[tid] = 0; }
    __syncthreads();

    int cellq[8], rankq[8];
    #pragma unroll
    for (int q = 0; q < 8; ++q) {
        const int e = q * 1024 + tid;
        const float2 p = pos[e];
        int cx = (int)(p.x * 16.0f); cx = cx < 0 ? 0 : (cx > 15 ? 15 : cx);
        int cy = (int)(p.y * 16.0f); cy = cy < 0 ? 0 : (cy > 15 ? 15 : cy);
        const int lx = (cy & 1) ? (15 - cx) : cx;          // snake order
        const int c  = (cy << 4) | lx;
        cellq[q] = c;
        rankq[q] = atomicAdd(&hist[c], 1);
    }
    __syncthreads();

    // exclusive scan of 256 cell counts (warps 0..7 active, others compute junk)
    {
        const int v = (tid < NCELL) ? hist[tid] : 0;
        int s = v;
        #pragma unroll
        for (int o = 1; o < 32; o <<= 1) {
            const int t = __shfl_up_sync(FULLM, s, o);
            if (lane >= o) s += t;
        }
        if (lane == 31 && w < 8) wsum[w] = s;
        __syncthreads();
        if (tid == 0) {
            int acc = 0;
            #pragma unroll
            for (int k = 0; k < 8; ++k) { wbase[k] = acc; acc += wsum[k]; }
        }
        __syncthreads();
        if (tid < NCELL) soff[tid] = wbase[w] + s - v;
        __syncthreads();
    }

    float* PV = (float*)g_pv;
    #pragma unroll
    for (int q = 0; q < 8; ++q) {
        const int e   = q * 1024 + tid;
        const int c   = cellq[q];
        const int dst = soff[c] + rankq[q];
        const float2 p = pos[e];
        const float2 v = vel[e];
        const int b = (dst >> 1) * 8 + (dst & 1);
        PV[b]     = p.x;
        PV[b + 2] = p.y;
        PV[b + 4] = v.x;
        PV[b + 6] = v.y;
        g_orig[dst] = e;
        ((unsigned char*)g_scellv)[dst] = (unsigned char)c;
    }
}

// ---------------- k1: cull + dual compact + pair math + ticketed epilogue ----------------
#define PAIR_MAIN(PJ, VJ)                                                     \
    {                                                                         \
        const u64 dx2 = f2add((PJ).x, nxi2);                                  \
        const u64 rxp = f2add(f2add(dx2, C2), nC2);                           \
        const u64 dwx = f2fma(rxp, nOne2, dx2);                               \
        const u64 dy2 = f2add((PJ).y, nyi2);                                  \
        const u64 ryp = f2add(f2add(dy2, C2), nC2);                           \
        const u64 dwy = f2fma(ryp, nOne2, dy2);                               \
        const u64 d2  = f2fma(dwy, dwy, f2mul(dwx, dwx));                     \
        const u64 mp  = f2mask(f2fma(d2, nOne2, perc2c), half2);              \
        Px2 = f2fma(dwx, mp, Px2);                                            \
        Py2 = f2fma(dwy, mp, Py2);                                            \
        Vx2 = f2fma((VJ).x, mp, Vx2);                                         \
        Vy2 = f2fma((VJ).y, mp, Vy2);                                         \
        Cn2 = f2add(Cn2, mp);                                                 \
    }

__global__ __launch_bounds__(TPB1)
void k1_main(const float2* __restrict__ vel,
             const float2* __restrict__ noise,
             const float*  __restrict__ w_sep,
             const float*  __restrict__ w_ali,
             const float*  __restrict__ w_coh,
             const float*  __restrict__ w_ns,
             float2*       __restrict__ out)
{
    __shared__ unsigned s_maskP[8];
    __shared__ unsigned s_maskS[8];
    __shared__ int      s_scanP[NWARP];
    __shared__ int      s_scanS[NWARP];
    __shared__ int      s_totalP, s_totalS, s_last;
    __shared__ __align__(8) u16 s_pairs[NB / 2];
    __shared__ u16      s_sep[NB / 2];
    __shared__ float    red[NWARP][32][8];

    const int tid    = threadIdx.x;
    const int lane   = tid & 31;
    const int w      = tid >> 5;
    const int g      = blockIdx.x >> 1;    // i-tile
    const int parity = blockIdx.x & 1;
    const int i      = g * 32 + lane;

    const float* P = (const float*)g_pv;
    const float pix = getX(P, i);
    const float piy = getY(P, i);

    // --- tile bbox ---
    const float x0 = __shfl_sync(FULLM, pix, 0);
    const float y0 = __shfl_sync(FULLM, piy, 0);
    const float rx = wrap1(pix - x0);
    const float ry = wrap1(piy - y0);
    float mnx = rx, mxx = rx, mny = ry, mxy = ry;
    #pragma unroll
    for (int o = 16; o; o >>= 1) {
        mnx = fminf(mnx, __shfl_xor_sync(FULLM, mnx, o));
        mxx = fmaxf(mxx, __shfl_xor_sync(FULLM, mxx, o));
        mny = fminf(mny, __shfl_xor_sync(FULLM, mny, o));
        mxy = fmaxf(mxy, __shfl_xor_sync(FULLM, mxy, o));
    }
    const float bcx = x0 + 0.5f * (mnx + mxx);
    const float bcy = y0 + 0.5f * (mny + mxy);
    const float bhx = 0.5f * (mxx - mnx);
    const float bhy = 0.5f * (mxy - mny);

    // --- cull: threads 0..255 test static rect of cell tid (both radii) ---
    if (tid < 256) {
        const int cy = tid >> 4;
        const int lx = tid & 15;
        const int cx = (cy & 1) ? (15 - lx) : lx;
        const float ccx = (cx + 0.5f) * (1.0f / 16.0f);
        const float ccy = (cy + 0.5f) * (1.0f / 16.0f);
        const float gx = fmaxf(0.0f, fabsf(wrap1(bcx - ccx)) - bhx - (1.0f / 32.0f) - 1e-5f);
        const float gy = fmaxf(0.0f, fabsf(wrap1(bcy - ccy)) - bhy - (1.0f / 32.0f) - 1e-5f);
        const float gap2 = gx * gx + gy * gy;
        const unsigned mP = __ballot_sync(FULLM, gap2 <= PERC2F);
        const unsigned mS = __ballot_sync(FULLM, gap2 <= SEP2F);
        if (lane == 0) { s_maskP[w] = mP; s_maskS[w] = mS; }
    }
    __syncthreads();

    // --- pair-level liveness: thread t owns pairs [8t,8t+8) = boids [16t,16t+16) ---
    unsigned plP = 0, plS = 0;
    {
        const uint4 cv = g_scellv[tid];
        const unsigned cw[4] = {cv.x, cv.y, cv.z, cv.w};
        #pragma unroll
        for (int q = 0; q < 4; ++q) {
            const unsigned word = cw[q];
            #pragma unroll
            for (int h = 0; h < 2; ++h) {
                const unsigned ca = (word >> (h * 16)) & 0xffu;
                const unsigned cb = (word >> (h * 16 + 8)) & 0xffu;
                const unsigned lvP = ((s_maskP[ca >> 5] >> (ca & 31)) |
                                      (s_maskP[cb >> 5] >> (cb & 31))) & 1u;
                const unsigned lvS = ((s_maskS[ca >> 5] >> (ca & 31)) |
                                      (s_maskS[cb >> 5] >> (cb & 31))) & 1u;
                plP |= lvP << (q * 2 + h);
                plS |= lvS << (q * 2 + h);
            }
        }
    }
    const int cntP = __popc(plP);
    const int cntS = __popc(plS);
    int sP = cntP, sS = cntS;
    #pragma unroll
    for (int o = 1; o < 32; o <<= 1) {
        const int tP = __shfl_up_sync(FULLM, sP, o);
        const int tS = __shfl_up_sync(FULLM, sS, o);
        if (lane >= o) { sP += tP; sS += tS; }
    }
    if (lane == 31) { s_scanP[w] = sP; s_scanS[w] = sS; }
    __syncthreads();
    if (tid == 0) {
        int aP = 0, aS = 0;
        #pragma unroll
        for (int k = 0; k < NWARP; ++k) {
            const int vP = s_scanP[k]; s_scanP[k] = aP; aP += vP;
            const int vS = s_scanS[k]; s_scanS[k] = aS; aS += vS;
        }
        s_totalP = aP; s_totalS = aS;
    }
    __syncthreads();
    {
        int oP = s_scanP[w] + sP - cntP;
        unsigned m2 = plP;
        while (m2) { const int b = __ffs(m2) - 1; m2 &= m2 - 1; s_pairs[oP++] = (u16)(tid * 8 + b); }
        int oS = s_scanS[w] + sS - cntS;
        m2 = plS;
        while (m2) { const int b = __ffs(m2) - 1; m2 &= m2 - 1; s_sep[oS++] = (u16)(tid * 8 + b); }
    }
    __syncthreads();
    const int total    = s_totalP;
    const int sepTotal = s_totalS;

    // --- constants & accumulators ---
    const u64 nxi2   = pack2(-pix, -pix);
    const u64 nyi2   = pack2(-piy, -piy);
    const u64 C2     = pack2( MAGIC,  MAGIC);
    const u64 nC2    = pack2(-MAGIC, -MAGIC);
    const u64 nOne2  = pack2(-1.0f, -1.0f);
    const u64 half2  = pack2(0.5f, 0.5f);
    const u64 sep2c  = pack2(SEP2F, SEP2F);
    const u64 perc2c = pack2(PERC2F, PERC2F);

    u64 Sx2 = 0, Sy2 = 0, Px2 = 0, Py2 = 0, Vx2 = 0, Vy2 = 0, Cn2 = 0;

    const ulonglong2* __restrict__ PV2 = (const ulonglong2*)g_pv;

    // --- main loop: segment sw of 32, 4-aligned boundaries, packed idx loads ---
    const int sw    = parity * NWARP + w;
    int k           = ((total * sw) >> 5) & ~3;
    const int kend4 = (sw == 31) ? (total & ~3) : (((total * (sw + 1)) >> 5) & ~3);

    for (; k < kend4; k += 4) {
        const uint2 pk = *(const uint2*)(s_pairs + k);
        const int i0 = pk.x & 0xffff;
        const int i1 = pk.x >> 16;
        const int i2 = pk.y & 0xffff;
        const int i3 = pk.y >> 16;
        const ulonglong2 pj0 = PV2[i0 * 2];
        const ulonglong2 vj0 = PV2[i0 * 2 + 1];
        const ulonglong2 pj1 = PV2[i1 * 2];
        const ulonglong2 vj1 = PV2[i1 * 2 + 1];
        const ulonglong2 pj2 = PV2[i2 * 2];
        const ulonglong2 vj2 = PV2[i2 * 2 + 1];
        const ulonglong2 pj3 = PV2[i3 * 2];
        const ulonglong2 vj3 = PV2[i3 * 2 + 1];
        PAIR_MAIN(pj0, vj0)
        PAIR_MAIN(pj1, vj1)
        PAIR_MAIN(pj2, vj2)
        PAIR_MAIN(pj3, vj3)
    }
    if (sw == 31) {
        for (k = total & ~3; k < total; ++k) {
            const int i0 = s_pairs[k];
            const ulonglong2 pj0 = PV2[i0 * 2];
            const ulonglong2 vj0 = PV2[i0 * 2 + 1];
            PAIR_MAIN(pj0, vj0)
        }
    }

    // --- separation side loop (tiny) ---
    for (int ks = sw; ks < sepTotal; ks += NSEG) {
        const int i0 = s_sep[ks];
        const ulonglong2 pj = PV2[i0 * 2];
        const u64 dx2 = f2add(pj.x, nxi2);
        const u64 rxp = f2add(f2add(dx2, C2), nC2);
        const u64 dwx = f2fma(rxp, nOne2, dx2);
        const u64 dy2 = f2add(pj.y, nyi2);
        const u64 ryp = f2add(f2add(dy2, C2), nC2);
        const u64 dwy = f2fma(ryp, nOne2, dy2);
        const u64 d2  = f2fma(dwy, dwy, f2mul(dwx, dwx));
        const u64 ms  = f2mask(f2fma(d2, nOne2, sep2c), half2);
        Sx2 = f2fma(dwx, ms, Sx2);
        Sy2 = f2fma(dwy, ms, Sy2);
    }

    // --- smem reduce (deterministic within block) ---
    float a, b;
    unpack2(Sx2, a, b);  red[w][lane][0] = a + b;
    unpack2(Sy2, a, b);  red[w][lane][1] = a + b;
    unpack2(Px2, a, b);  red[w][lane][2] = a + b;
    unpack2(Py2, a, b);  red[w][lane][3] = a + b;
    unpack2(Vx2, a, b);  red[w][lane][4] = a + b;
    unpack2(Vy2, a, b);  red[w][lane][5] = a + b;
    unpack2(Cn2, a, b);  red[w][lane][6] = a + b;
    __syncthreads();

    float s7[7];
    if (tid < 32) {
        #pragma unroll
        for (int comp = 0; comp < 7; ++comp) {
            float acc = 0.0f;
            #pragma unroll
            for (int sg = 0; sg < NWARP; ++sg) acc += red[sg][tid][comp];
            s7[comp] = acc;
            g_part[parity][comp][g * 32 + tid] = acc;
        }
        __threadfence();
    }
    __syncthreads();
    if (tid == 0) {
        const int old = atomicAdd(&g_ticket[g], 1);
        s_last = (old == 1);
    }
    __syncthreads();

    if (s_last && tid < 32) {
        __threadfence();
        #pragma unroll
        for (int comp = 0; comp < 7; ++comp)
            s7[comp] += g_part[1 - parity][comp][g * 32 + tid];

        const float Sx = s7[0], Sy = s7[1], Px = s7[2], Py = s7[3];
        const float Vx = s7[4], Vy = s7[5];
        const float C  = s7[6] - 1.0f;       // remove self

        const int orig = g_orig[g * 32 + tid];
        const float2 vi = vel[orig];
        const float2 nz = noise[orig];

        float nrm = sqrtf(Sx * Sx + Sy * Sy);
        float inv = 1.0f / fmaxf(nrm, EPSF);
        const float sepx = -Sx * inv;
        const float sepy = -Sy * inv;

        const float invC = 1.0f / C;

        const float avx = (Vx - vi.x) * invC - vi.x;
        const float avy = (Vy - vi.y) * invC - vi.y;
        nrm = sqrtf(avx * avx + avy * avy);
        inv = 1.0f / fmaxf(nrm, EPSF);
        const float alix = avx * inv;
        const float aliy = avy * inv;

        const float cx2 = Px * invC;
        const float cy2 = Py * invC;
        nrm = sqrtf(cx2 * cx2 + cy2 * cy2);
        inv = 1.0f / fmaxf(nrm, EPSF);
        const float cohx = cx2 * inv;
        const float cohy = cy2 * inv;

        const float ws = *w_sep;
        const float wa = *w_ali;
        const float wc = *w_coh;
        const float wn = *w_ns;

        float ax = ws * sepx + wa * alix + wc * cohx + wn * nz.x;
        float ay = ws * sepy + wa * aliy + wc * cohy + wn * nz.y;

        nrm = sqrtf(ax * ax + ay * ay);
        if (nrm > 1.0f) {
            const float sc = 1.0f / fmaxf(nrm, EPSF);
            ax *= sc;
            ay *= sc;
        }

        out[orig] = make_float2(ax, ay);
    }
}

extern "C" void kernel_launch(void* const* d_in, const int* in_sizes, int n_in,
                              void* d_out, int out_size)
{
    const float2* pos   = (const float2*)d_in[0];
    const float2* vel   = (const float2*)d_in[1];
    const float2* noise = (const float2*)d_in[2];
    const float*  wsep  = (const float*)d_in[3];
    const float*  wali  = (const float*)d_in[4];
    const float*  wcoh  = (const float*)d_in[5];
    const float*  wns   = (const float*)d_in[6];
    float2* out = (float2*)d_out;

    kS_sort<<<1, 1024>>>(pos, vel);
    k1_main<<<NTILE * 2, TPB1>>>(vel, noise, wsep, wali, wcoh, wns, out);
}

// round 11
// speedup vs baseline: 1.6422x; 1.6422x over previous
#include <cuda_runtime.h>

// BoidPolicy: all-pairs boids on a unit torus, N=8192, out acc [N,2] f32.
//
// Pipeline (graph-capturable, allocation-free, 3 launches):
//  kAB: 32 blocks: 16x16 snake cells + smem-atomic ranks + per-block histograms;
//       last-arriving block (ticket) computes the 256-cell prefix -> g_off
//  kC:  32 blocks: scatter into interleaved pos/vel records + cell bytes + orig idx
//  k1:  TWO blocks per 32-i tile (512 thr): cull cells vs tile bbox (perc AND sep)
//       -> two compacted pair lists -> perception main loop (packed f32x2,
//       unroll-4, packed index loads) + tiny separation loop -> reduce ->
//       parity-ticketed fused epilogue.

#define NB      8192
#define NCELL   256
#define NBLKA   32
#define NTILE   256
#define TPB1    512
#define NWARP   16            // warps per block
#define NSEG    32            // segments per tile (2 blocks x 16 warps)

#define SEP2F   4e-4f
#define PERC2F  0.04f
#define EPSF    1e-8f
#define MAGIC   12582912.0f   // 1.5 * 2^23
#define FULLM   0xffffffffu

typedef unsigned long long u64;
typedef unsigned short u16;

__device__ float4 g_pv[NB];             // pair p: [2p]=(xA,xB,yA,yB), [2p+1]=(vxA,vxB,vyA,vyB)
__device__ int    g_orig[NB];
__device__ uint4  g_scellv[NB / 16];    // sorted cell ids, 1 byte per boid
__device__ int    g_cellid[NB];
__device__ int    g_lrank[NB];
__device__ int    g_cnt[NBLKA * NCELL];
__device__ int    g_off[NBLKA * NCELL];
__device__ float  g_part[2][7][NB];     // [parity][comp][sorted boid]
__device__ int    g_ticket[NTILE];      // monotonically increasing; parity selects
__device__ int    g_tkA;                // kAB ticket (mod 32)

__device__ __forceinline__ u64 pack2(float lo, float hi) {
    u64 r; asm("mov.b64 %0,{%1,%2};" : "=l"(r) : "f"(lo), "f"(hi)); return r;
}
__device__ __forceinline__ void unpack2(u64 v, float& lo, float& hi) {
    asm("mov.b64 {%0,%1},%2;" : "=f"(lo), "=f"(hi) : "l"(v));
}
__device__ __forceinline__ u64 f2add(u64 a, u64 b) {
    u64 d; asm("add.rn.f32x2 %0,%1,%2;" : "=l"(d) : "l"(a), "l"(b)); return d;
}
__device__ __forceinline__ u64 f2mul(u64 a, u64 b) {
    u64 d; asm("mul.rn.f32x2 %0,%1,%2;" : "=l"(d) : "l"(a), "l"(b)); return d;
}
__device__ __forceinline__ u64 f2fma(u64 a, u64 b, u64 c) {
    u64 d; asm("fma.rn.f32x2 %0,%1,%2,%3;" : "=l"(d) : "l"(a), "l"(b), "l"(c)); return d;
}
// per-half: (t >= 0) ? 1.0f : 0.0f  (exact: copysign(0.5,t)+0.5)
__device__ __forceinline__ u64 f2mask(u64 t, u64 half2) {
    u64 s = (t & 0x8000000080000000ULL) | 0x3F0000003F000000ULL;
    return f2add(s, half2);
}
__device__ __forceinline__ float wrap1(float d) { return d - rintf(d); }
__device__ __forceinline__ float getX(const float* P, int idx) {
    return P[(idx >> 1) * 8 + (idx & 1)];
}
__device__ __forceinline__ float getY(const float* P, int idx) {
    return P[(idx >> 1) * 8 + 2 + (idx & 1)];
}

// ---------------- kAB: cells + ranks + histograms; last block does prefix ----------------
__global__ void kAB_cells(const float2* __restrict__ pos)
{
    __shared__ int hist[NCELL];
    __shared__ int s_last;
    const int tid = threadIdx.x;
    hist[tid] = 0;
    __syncthreads();

    const int e = blockIdx.x * 256 + tid;
    const float2 p = pos[e];
    int cx = (int)(p.x * 16.0f); cx = cx < 0 ? 0 : (cx > 15 ? 15 : cx);
    int cy = (int)(p.y * 16.0f); cy = cy < 0 ? 0 : (cy > 15 ? 15 : cy);
    const int lx   = (cy & 1) ? (15 - cx) : cx;       // snake order
    const int cell = (cy << 4) | lx;

    const int r = atomicAdd(&hist[cell], 1);
    g_cellid[e] = cell;
    g_lrank[e]  = r;
    __syncthreads();

    g_cnt[blockIdx.x * NCELL + tid] = hist[tid];
    __threadfence();
    __syncthreads();
    if (tid == 0) {
        const int old = atomicAdd(&g_tkA, 1);
        s_last = ((old & 31) == 31);               // mod-32 ticket: no reset needed
    }
    __syncthreads();
    if (!s_last) return;

    // last block computes scatter offsets (256 threads, one per cell)
    const int c = tid;
    int run = 0;
    for (int g = 0; g < NBLKA; ++g) {
        const int v = g_cnt[g * NCELL + c];
        g_off[g * NCELL + c] = run;
        run += v;
    }
    __shared__ int wsum[8];
    __shared__ int wbase[8];
    const int lane = c & 31, w = c >> 5;
    int s = run;
    #pragma unroll
    for (int o = 1; o < 32; o <<= 1) {
        const int t = __shfl_up_sync(FULLM, s, o);
        if (lane >= o) s += t;
    }
    if (lane == 31) wsum[w] = s;
    __syncthreads();
    if (c == 0) {
        int acc = 0;
        #pragma unroll
        for (int k = 0; k < 8; ++k) { wbase[k] = acc; acc += wsum[k]; }
    }
    __syncthreads();
    const int base = wbase[w] + s - run;
    for (int g = 0; g < NBLKA; ++g) g_off[g * NCELL + c] += base;
}

// ---------------- kC: scatter into interleaved sorted records ----------------
__global__ void kC_scatter(const float2* __restrict__ pos,
                           const float2* __restrict__ vel)
{
    const int e    = blockIdx.x * 256 + threadIdx.x;
    const int cell = g_cellid[e];
    const int dst  = g_off[(e >> 8) * NCELL + cell] + g_lrank[e];
    const float2 p = pos[e];
    const float2 v = vel[e];
    float* PV = (float*)g_pv;
    const int b = (dst >> 1) * 8 + (dst & 1);
    PV[b]     = p.x;
    PV[b + 2] = p.y;
    PV[b + 4] = v.x;
    PV[b + 6] = v.y;
    g_orig[dst] = e;
    ((unsigned char*)g_scellv)[dst] = (unsigned char)cell;
}

// ---------------- k1: cull + dual compact + pair math + ticketed epilogue ----------------
#define PAIR_MAIN(PJ, VJ)                                                     \
    {                                                                         \
        const u64 dx2 = f2add((PJ).x, nxi2);                                  \
        const u64 rxp = f2add(f2add(dx2, C2), nC2);                           \
        const u64 dwx = f2fma(rxp, nOne2, dx2);                               \
        const u64 dy2 = f2add((PJ).y, nyi2);                                  \
        const u64 ryp = f2add(f2add(dy2, C2), nC2);                           \
        const u64 dwy = f2fma(ryp, nOne2, dy2);                               \
        const u64 d2  = f2fma(dwy, dwy, f2mul(dwx, dwx));                     \
        const u64 mp  = f2mask(f2fma(d2, nOne2, perc2c), half2);              \
        Px2 = f2fma(dwx, mp, Px2);                                            \
        Py2 = f2fma(dwy, mp, Py2);                                            \
        Vx2 = f2fma((VJ).x, mp, Vx2);                                         \
        Vy2 = f2fma((VJ).y, mp, Vy2);                                         \
        Cn2 = f2add(Cn2, mp);                                                 \
    }

__global__ __launch_bounds__(TPB1, 3)
void k1_main(const float2* __restrict__ vel,
             const float2* __restrict__ noise,
             const float*  __restrict__ w_sep,
             const float*  __restrict__ w_ali,
             const float*  __restrict__ w_coh,
             const float*  __restrict__ w_ns,
             float2*       __restrict__ out)
{
    __shared__ unsigned s_maskP[8];
    __shared__ unsigned s_maskS[8];
    __shared__ int      s_scanP[NWARP];
    __shared__ int      s_scanS[NWARP];
    __shared__ int      s_totalP, s_totalS, s_last;
    __shared__ __align__(8) u16 s_pairs[NB / 2];
    __shared__ u16      s_sep[NB / 2];
    __shared__ float    red[NWARP][32][8];

    const int tid    = threadIdx.x;
    const int lane   = tid & 31;
    const int w      = tid >> 5;
    const int g      = blockIdx.x >> 1;    // i-tile
    const int parity = blockIdx.x & 1;
    const int i      = g * 32 + lane;

    const float* P = (const float*)g_pv;
    const float pix = getX(P, i);
    const float piy = getY(P, i);

    // --- tile bbox ---
    const float x0 = __shfl_sync(FULLM, pix, 0);
    const float y0 = __shfl_sync(FULLM, piy, 0);
    const float rx = wrap1(pix - x0);
    const float ry = wrap1(piy - y0);
    float mnx = rx, mxx = rx, mny = ry, mxy = ry;
    #pragma unroll
    for (int o = 16; o; o >>= 1) {
        mnx = fminf(mnx, __shfl_xor_sync(FULLM, mnx, o));
        mxx = fmaxf(mxx, __shfl_xor_sync(FULLM, mxx, o));
        mny = fminf(mny, __shfl_xor_sync(FULLM, mny, o));
        mxy = fmaxf(mxy, __shfl_xor_sync(FULLM, mxy, o));
    }
    const float bcx = x0 + 0.5f * (mnx + mxx);
    const float bcy = y0 + 0.5f * (mny + mxy);
    const float bhx = 0.5f * (mxx - mnx);
    const float bhy = 0.5f * (mxy - mny);

    // --- cull: threads 0..255 test static rect of cell tid (both radii) ---
    if (tid < 256) {
        const int cy = tid >> 4;
        const int lx = tid & 15;
        const int cx = (cy & 1) ? (15 - lx) : lx;
        const float ccx = (cx + 0.5f) * (1.0f / 16.0f);
        const float ccy = (cy + 0.5f) * (1.0f / 16.0f);
        const float gx = fmaxf(0.0f, fabsf(wrap1(bcx - ccx)) - bhx - (1.0f / 32.0f) - 1e-5f);
        const float gy = fmaxf(0.0f, fabsf(wrap1(bcy - ccy)) - bhy - (1.0f / 32.0f) - 1e-5f);
        const float gap2 = gx * gx + gy * gy;
        const unsigned mP = __ballot_sync(FULLM, gap2 <= PERC2F);
        const unsigned mS = __ballot_sync(FULLM, gap2 <= SEP2F);
        if (lane == 0) { s_maskP[w] = mP; s_maskS[w] = mS; }
    }
    __syncthreads();

    // --- pair-level liveness: thread t owns pairs [8t,8t+8) = boids [16t,16t+16) ---
    unsigned plP = 0, plS = 0;
    {
        const uint4 cv = g_scellv[tid];
        const unsigned cw[4] = {cv.x, cv.y, cv.z, cv.w};
        #pragma unroll
        for (int q = 0; q < 4; ++q) {
            const unsigned word = cw[q];
            #pragma unroll
            for (int h = 0; h < 2; ++h) {
                const unsigned ca = (word >> (h * 16)) & 0xffu;
                const unsigned cb = (word >> (h * 16 + 8)) & 0xffu;
                const unsigned lvP = ((s_maskP[ca >> 5] >> (ca & 31)) |
                                      (s_maskP[cb >> 5] >> (cb & 31))) & 1u;
                const unsigned lvS = ((s_maskS[ca >> 5] >> (ca & 31)) |
                                      (s_maskS[cb >> 5] >> (cb & 31))) & 1u;
                plP |= lvP << (q * 2 + h);
                plS |= lvS << (q * 2 + h);
            }
        }
    }
    const int cntP = __popc(plP);
    const int cntS = __popc(plS);
    int sP = cntP, sS = cntS;
    #pragma unroll
    for (int o = 1; o < 32; o <<= 1) {
        const int tP = __shfl_up_sync(FULLM, sP, o);
        const int tS = __shfl_up_sync(FULLM, sS, o);
        if (lane >= o) { sP += tP; sS += tS; }
    }
    if (lane == 31) { s_scanP[w] = sP; s_scanS[w] = sS; }
    __syncthreads();
    if (tid == 0) {
        int aP = 0, aS = 0;
        #pragma unroll
        for (int k = 0; k < NWARP; ++k) {
            const int vP = s_scanP[k]; s_scanP[k] = aP; aP += vP;
            const int vS = s_scanS[k]; s_scanS[k] = aS; aS += vS;
        }
        s_totalP = aP; s_totalS = aS;
    }
    __syncthreads();
    {
        int oP = s_scanP[w] + sP - cntP;
        unsigned m2 = plP;
        while (m2) { const int b = __ffs(m2) - 1; m2 &= m2 - 1; s_pairs[oP++] = (u16)(tid * 8 + b); }
        int oS = s_scanS[w] + sS - cntS;
        m2 = plS;
        while (m2) { const int b = __ffs(m2) - 1; m2 &= m2 - 1; s_sep[oS++] = (u16)(tid * 8 + b); }
    }
    __syncthreads();
    const int total    = s_totalP;
    const int sepTotal = s_totalS;

    // --- constants & accumulators ---
    const u64 nxi2   = pack2(-pix, -pix);
    const u64 nyi2   = pack2(-piy, -piy);
    const u64 C2     = pack2( MAGIC,  MAGIC);
    const u64 nC2    = pack2(-MAGIC, -MAGIC);
    const u64 nOne2  = pack2(-1.0f, -1.0f);
    const u64 half2  = pack2(0.5f, 0.5f);
    const u64 sep2c  = pack2(SEP2F, SEP2F);
    const u64 perc2c = pack2(PERC2F, PERC2F);

    u64 Sx2 = 0, Sy2 = 0, Px2 = 0, Py2 = 0, Vx2 = 0, Vy2 = 0, Cn2 = 0;

    const ulonglong2* __restrict__ PV2 = (const ulonglong2*)g_pv;

    // --- main loop: segment sw of 32, 4-aligned boundaries, packed idx loads ---
    const int sw    = parity * NWARP + w;
    int k           = ((total * sw) >> 5) & ~3;
    const int kend4 = (sw == 31) ? (total & ~3) : (((total * (sw + 1)) >> 5) & ~3);

    for (; k < kend4; k += 4) {
        const uint2 pk = *(const uint2*)(s_pairs + k);
        const int i0 = pk.x & 0xffff;
        const int i1 = pk.x >> 16;
        const int i2 = pk.y & 0xffff;
        const int i3 = pk.y >> 16;
        const ulonglong2 pj0 = PV2[i0 * 2];
        const ulonglong2 vj0 = PV2[i0 * 2 + 1];
        const ulonglong2 pj1 = PV2[i1 * 2];
        const ulonglong2 vj1 = PV2[i1 * 2 + 1];
        const ulonglong2 pj2 = PV2[i2 * 2];
        const ulonglong2 vj2 = PV2[i2 * 2 + 1];
        const ulonglong2 pj3 = PV2[i3 * 2];
        const ulonglong2 vj3 = PV2[i3 * 2 + 1];
        PAIR_MAIN(pj0, vj0)
        PAIR_MAIN(pj1, vj1)
        PAIR_MAIN(pj2, vj2)
        PAIR_MAIN(pj3, vj3)
    }
    if (sw == 31) {
        for (k = total & ~3; k < total; ++k) {
            const int i0 = s_pairs[k];
            const ulonglong2 pj0 = PV2[i0 * 2];
            const ulonglong2 vj0 = PV2[i0 * 2 + 1];
            PAIR_MAIN(pj0, vj0)
        }
    }

    // --- separation side loop (tiny: sep radius = 0.02) ---
    for (int ks = sw; ks < sepTotal; ks += NSEG) {
        const int i0 = s_sep[ks];
        const ulonglong2 pj = PV2[i0 * 2];
        const u64 dx2 = f2add(pj.x, nxi2);
        const u64 rxp = f2add(f2add(dx2, C2), nC2);
        const u64 dwx = f2fma(rxp, nOne2, dx2);
        const u64 dy2 = f2add(pj.y, nyi2);
        const u64 ryp = f2add(f2add(dy2, C2), nC2);
        const u64 dwy = f2fma(ryp, nOne2, dy2);
        const u64 d2  = f2fma(dwy, dwy, f2mul(dwx, dwx));
        const u64 ms  = f2mask(f2fma(d2, nOne2, sep2c), half2);
        Sx2 = f2fma(dwx, ms, Sx2);
        Sy2 = f2fma(dwy, ms, Sy2);
    }

    // --- smem reduce (deterministic within block) ---
    float a, b;
    unpack2(Sx2, a, b);  red[w][lane][0] = a + b;
    unpack2(Sy2, a, b);  red[w][lane][1] = a + b;
    unpack2(Px2, a, b);  red[w][lane][2] = a + b;
    unpack2(Py2, a, b);  red[w][lane][3] = a + b;
    unpack2(Vx2, a, b);  red[w][lane][4] = a + b;
    unpack2(Vy2, a, b);  red[w][lane][5] = a + b;
    unpack2(Cn2, a, b);  red[w][lane][6] = a + b;
    __syncthreads();

    float s7[7];
    if (tid < 32) {
        #pragma unroll
        for (int comp = 0; comp < 7; ++comp) {
            float acc = 0.0f;
            #pragma unroll
            for (int sg = 0; sg < NWARP; ++sg) acc += red[sg][tid][comp];
            s7[comp] = acc;
            g_part[parity][comp][g * 32 + tid] = acc;
        }
        __threadfence();
    }
    __syncthreads();
    if (tid == 0) {
        const int old = atomicAdd(&g_ticket[g], 1);
        s_last = (old & 1);                    // 2 arrivals per run; parity selects last
    }
    __syncthreads();

    if (s_last && tid < 32) {
        __threadfence();
        // combine: part0 + part1 (fp add commutative -> same value either way)
        #pragma unroll
        for (int comp = 0; comp < 7; ++comp)
            s7[comp] += g_part[1 - parity][comp][g * 32 + tid];

        const float Sx = s7[0], Sy = s7[1], Px = s7[2], Py = s7[3];
        const float Vx = s7[4], Vy = s7[5];
        const float C  = s7[6] - 1.0f;         // remove self

        const int orig = g_orig[g * 32 + tid];
        const float2 vi = vel[orig];
        const float2 nz = noise[orig];

        float nrm = sqrtf(Sx * Sx + Sy * Sy);
        float inv = 1.0f / fmaxf(nrm, EPSF);
        const float sepx = -Sx * inv;
        const float sepy = -Sy * inv;

        const float invC = 1.0f / C;

        const float avx = (Vx - vi.x) * invC - vi.x;
        const float avy = (Vy - vi.y) * invC - vi.y;
        nrm = sqrtf(avx * avx + avy * avy);
        inv = 1.0f / fmaxf(nrm, EPSF);
        const float alix = avx * inv;
        const float aliy = avy * inv;

        const float cx2 = Px * invC;
        const float cy2 = Py * invC;
        nrm = sqrtf(cx2 * cx2 + cy2 * cy2);
        inv = 1.0f / fmaxf(nrm, EPSF);
        const float cohx = cx2 * inv;
        const float cohy = cy2 * inv;

        const float ws = *w_sep;
        const float wa = *w_ali;
        const float wc = *w_coh;
        const float wn = *w_ns;

        float ax = ws * sepx + wa * alix + wc * cohx + wn * nz.x;
        float ay = ws * sepy + wa * aliy + wc * cohy + wn * nz.y;

        nrm = sqrtf(ax * ax + ay * ay);
        if (nrm > 1.0f) {
            const float sc = 1.0f / fmaxf(nrm, EPSF);
            ax *= sc;
            ay *= sc;
        }

        out[orig] = make_float2(ax, ay);
    }
}

extern "C" void kernel_launch(void* const* d_in, const int* in_sizes, int n_in,
                              void* d_out, int out_size)
{
    const float2* pos   = (const float2*)d_in[0];
    const float2* vel   = (const float2*)d_in[1];
    const float2* noise = (const float2*)d_in[2];
    const float*  wsep  = (const float*)d_in[3];
    const float*  wali  = (const float*)d_in[4];
    const float*  wcoh  = (const float*)d_in[5];
    const float*  wns   = (const float*)d_in[6];
    float2* out = (float2*)d_out;

    kAB_cells <<<NBLKA, 256>>>(pos);
    kC_scatter<<<NBLKA, 256>>>(pos, vel);
    k1_main   <<<NTILE * 2, TPB1>>>(vel, noise, wsep, wali, wcoh, wns, out);
}

// round 12
// speedup vs baseline: 1.7300x; 1.0535x over previous
#include <cuda_runtime.h>

// BoidPolicy: all-pairs boids on a unit torus, N=8192, out acc [N,2] f32.
//
// Pipeline (graph-capturable, allocation-free, 3 launches):
//  kA: 16x16 snake cells + smem-atomic ranks + per-block histograms
//  kC: per-block redundant offset computation (no cross-block prefix dependency)
//      + scatter into interleaved pos/vel pair records
//  k1: TWO blocks per 32-i tile (512 thr): per-PAIR bbox cull vs tile bbox
//      (perception AND separation radii) -> two compacted pair lists ->
//      perception main loop (packed f32x2, unroll-4, packed index loads)
//      + tiny separation loop -> reduce -> parity-ticketed fused epilogue.

#define NB      8192
#define NCELL   256
#define NBLKA   32
#define NTILE   256
#define TPB1    512
#define NWARP   16            // warps per block
#define NSEG    32            // segments per tile (2 blocks x 16 warps)

#define SEP2F   4e-4f
#define PERC2F  0.04f
#define EPSF    1e-8f
#define MAGIC   12582912.0f   // 1.5 * 2^23
#define FULLM   0xffffffffu

typedef unsigned long long u64;
typedef unsigned short u16;

__device__ float4 g_pv[NB];             // pair p: [2p]=(xA,xB,yA,yB), [2p+1]=(vxA,vxB,vyA,vyB)
__device__ int    g_orig[NB];
__device__ int    g_cellid[NB];
__device__ int    g_lrank[NB];
__device__ int    g_cnt[NBLKA * NCELL];
__device__ float  g_part[2][7][NB];     // [parity][comp][sorted boid]
__device__ int    g_ticket[NTILE];      // +2 per run; parity selects last arrival

__device__ __forceinline__ u64 pack2(float lo, float hi) {
    u64 r; asm("mov.b64 %0,{%1,%2};" : "=l"(r) : "f"(lo), "f"(hi)); return r;
}
__device__ __forceinline__ void unpack2(u64 v, float& lo, float& hi) {
    asm("mov.b64 {%0,%1},%2;" : "=f"(lo), "=f"(hi) : "l"(v));
}
__device__ __forceinline__ u64 f2add(u64 a, u64 b) {
    u64 d; asm("add.rn.f32x2 %0,%1,%2;" : "=l"(d) : "l"(a), "l"(b)); return d;
}
__device__ __forceinline__ u64 f2mul(u64 a, u64 b) {
    u64 d; asm("mul.rn.f32x2 %0,%1,%2;" : "=l"(d) : "l"(a), "l"(b)); return d;
}
__device__ __forceinline__ u64 f2fma(u64 a, u64 b, u64 c) {
    u64 d; asm("fma.rn.f32x2 %0,%1,%2,%3;" : "=l"(d) : "l"(a), "l"(b), "l"(c)); return d;
}
// per-half: (t >= 0) ? 1.0f : 0.0f  (exact: copysign(0.5,t)+0.5)
__device__ __forceinline__ u64 f2mask(u64 t, u64 half2) {
    u64 s = (t & 0x8000000080000000ULL) | 0x3F0000003F000000ULL;
    return f2add(s, half2);
}
__device__ __forceinline__ float wrap1(float d) { return d - rintf(d); }
__device__ __forceinline__ float getX(const float* P, int idx) {
    return P[(idx >> 1) * 8 + (idx & 1)];
}
__device__ __forceinline__ float getY(const float* P, int idx) {
    return P[(idx >> 1) * 8 + 2 + (idx & 1)];
}

// ---------------- kA: cell ids + ranks + per-block histograms ----------------
__global__ void kA_cells(const float2* __restrict__ pos)
{
    __shared__ int hist[NCELL];
    const int tid = threadIdx.x;
    hist[tid] = 0;
    __syncthreads();

    const int e = blockIdx.x * 256 + tid;
    const float2 p = pos[e];
    int cx = (int)(p.x * 16.0f); cx = cx < 0 ? 0 : (cx > 15 ? 15 : cx);
    int cy = (int)(p.y * 16.0f); cy = cy < 0 ? 0 : (cy > 15 ? 15 : cy);
    const int lx   = (cy & 1) ? (15 - cx) : cx;       // snake order
    const int cell = (cy << 4) | lx;

    const int r = atomicAdd(&hist[cell], 1);
    g_cellid[e] = cell;
    g_lrank[e]  = r;
    __syncthreads();

    g_cnt[blockIdx.x * NCELL + tid] = hist[tid];
}

// ---------------- kC: per-block redundant offsets + scatter ----------------
__global__ void kC_scatter(const float2* __restrict__ pos,
                           const float2* __restrict__ vel)
{
    __shared__ int s_off[NCELL];
    __shared__ int wsum[8];
    __shared__ int wbase[8];

    const int tid  = threadIdx.x;      // doubles as cell index for the scan
    const int lane = tid & 31;
    const int w    = tid >> 5;
    const int b    = blockIdx.x;

    // thread c: total count of cell c, and partial sum over earlier blocks
    int tot = 0, part = 0;
    #pragma unroll
    for (int g = 0; g < NBLKA; ++g) {
        const int v = g_cnt[g * NCELL + tid];
        tot += v;
        if (g < b) part += v;
    }
    // exclusive scan of per-cell totals across 256 threads
    int s = tot;
    #pragma unroll
    for (int o = 1; o < 32; o <<= 1) {
        const int t = __shfl_up_sync(FULLM, s, o);
        if (lane >= o) s += t;
    }
    if (lane == 31) wsum[w] = s;
    __syncthreads();
    if (tid == 0) {
        int acc = 0;
        #pragma unroll
        for (int k = 0; k < 8; ++k) { wbase[k] = acc; acc += wsum[k]; }
    }
    __syncthreads();
    s_off[tid] = wbase[w] + s - tot + part;
    __syncthreads();

    // scatter this block's boid
    const int e    = b * 256 + tid;
    const int cell = g_cellid[e];
    const int dst  = s_off[cell] + g_lrank[e];
    const float2 p = pos[e];
    const float2 v = vel[e];
    float* PV = (float*)g_pv;
    const int bb = (dst >> 1) * 8 + (dst & 1);
    PV[bb]     = p.x;
    PV[bb + 2] = p.y;
    PV[bb + 4] = v.x;
    PV[bb + 6] = v.y;
    g_orig[dst] = e;
}

// ---------------- k1: pair-bbox cull + dual compact + pair math + epilogue ----------------
#define PAIR_MAIN(PJ, VJ)                                                     \
    {                                                                         \
        const u64 dx2 = f2add((PJ).x, nxi2);                                  \
        const u64 rxp = f2add(f2add(dx2, C2), nC2);                           \
        const u64 dwx = f2fma(rxp, nOne2, dx2);                               \
        const u64 dy2 = f2add((PJ).y, nyi2);                                  \
        const u64 ryp = f2add(f2add(dy2, C2), nC2);                           \
        const u64 dwy = f2fma(ryp, nOne2, dy2);                               \
        const u64 d2  = f2fma(dwy, dwy, f2mul(dwx, dwx));                     \
        const u64 mp  = f2mask(f2fma(d2, nOne2, perc2c), half2);              \
        Px2 = f2fma(dwx, mp, Px2);                                            \
        Py2 = f2fma(dwy, mp, Py2);                                            \
        Vx2 = f2fma((VJ).x, mp, Vx2);                                         \
        Vy2 = f2fma((VJ).y, mp, Vy2);                                         \
        Cn2 = f2add(Cn2, mp);                                                 \
    }

__global__ __launch_bounds__(TPB1, 3)
void k1_main(const float2* __restrict__ vel,
             const float2* __restrict__ noise,
             const float*  __restrict__ w_sep,
             const float*  __restrict__ w_ali,
             const float*  __restrict__ w_coh,
             const float*  __restrict__ w_ns,
             float2*       __restrict__ out)
{
    __shared__ int      s_scanP[NWARP];
    __shared__ int      s_scanS[NWARP];
    __shared__ int      s_totalP, s_totalS, s_last;
    __shared__ __align__(8) u16 s_pairs[NB / 2];
    __shared__ u16      s_sep[NB / 2];
    __shared__ float    red[NWARP][32][8];

    const int tid    = threadIdx.x;
    const int lane   = tid & 31;
    const int w      = tid >> 5;
    const int g      = blockIdx.x >> 1;    // i-tile
    const int parity = blockIdx.x & 1;
    const int i      = g * 32 + lane;

    const float* P = (const float*)g_pv;
    const float pix = getX(P, i);
    const float piy = getY(P, i);

    // --- tile bbox (each warp computes an identical copy via shuffles) ---
    const float x0 = __shfl_sync(FULLM, pix, 0);
    const float y0 = __shfl_sync(FULLM, piy, 0);
    const float rx = wrap1(pix - x0);
    const float ry = wrap1(piy - y0);
    float mnx = rx, mxx = rx, mny = ry, mxy = ry;
    #pragma unroll
    for (int o = 16; o; o >>= 1) {
        mnx = fminf(mnx, __shfl_xor_sync(FULLM, mnx, o));
        mxx = fmaxf(mxx, __shfl_xor_sync(FULLM, mxx, o));
        mny = fminf(mny, __shfl_xor_sync(FULLM, mny, o));
        mxy = fmaxf(mxy, __shfl_xor_sync(FULLM, mxy, o));
    }
    const float bcx = x0 + 0.5f * (mnx + mxx);
    const float bcy = y0 + 0.5f * (mny + mxy);
    const float mrgx = 0.5f * (mxx - mnx) + 1e-5f;   // tile half-extent + slack
    const float mrgy = 0.5f * (mxy - mny) + 1e-5f;

    // --- pair-bbox liveness: thread t tests pairs [8t, 8t+8) directly ---
    // Pair boids are snake-sort adjacent (<= 2 adjacent cells, never wrapped),
    // so the flat min/max bbox is exact; toroidal box-gap test is conservative.
    unsigned plP = 0, plS = 0;
    #pragma unroll
    for (int q = 0; q < 8; ++q) {
        const int p = tid * 8 + q;
        const float4 r4 = g_pv[p * 2];          // (xA, xB, yA, yB)
        const float pmnx = fminf(r4.x, r4.y), pmxx = fmaxf(r4.x, r4.y);
        const float pmny = fminf(r4.z, r4.w), pmxy = fmaxf(r4.z, r4.w);
        const float pcx = 0.5f * (pmnx + pmxx);
        const float phx = 0.5f * (pmxx - pmnx);
        const float pcy = 0.5f * (pmny + pmxy);
        const float phy = 0.5f * (pmxy - pmny);
        const float gx = fmaxf(0.0f, fabsf(wrap1(bcx - pcx)) - mrgx - phx);
        const float gy = fmaxf(0.0f, fabsf(wrap1(bcy - pcy)) - mrgy - phy);
        const float gap2 = gx * gx + gy * gy;
        plP |= (gap2 <= PERC2F ? 1u : 0u) << q;
        plS |= (gap2 <= SEP2F  ? 1u : 0u) << q;
    }

    const int cntP = __popc(plP);
    const int cntS = __popc(plS);
    int sP = cntP, sS = cntS;
    #pragma unroll
    for (int o = 1; o < 32; o <<= 1) {
        const int tP = __shfl_up_sync(FULLM, sP, o);
        const int tS = __shfl_up_sync(FULLM, sS, o);
        if (lane >= o) { sP += tP; sS += tS; }
    }
    if (lane == 31) { s_scanP[w] = sP; s_scanS[w] = sS; }
    __syncthreads();
    if (tid == 0) {
        int aP = 0, aS = 0;
        #pragma unroll
        for (int k = 0; k < NWARP; ++k) {
            const int vP = s_scanP[k]; s_scanP[k] = aP; aP += vP;
            const int vS = s_scanS[k]; s_scanS[k] = aS; aS += vS;
        }
        s_totalP = aP; s_totalS = aS;
    }
    __syncthreads();
    {
        int oP = s_scanP[w] + sP - cntP;
        unsigned m2 = plP;
        while (m2) { const int b = __ffs(m2) - 1; m2 &= m2 - 1; s_pairs[oP++] = (u16)(tid * 8 + b); }
        int oS = s_scanS[w] + sS - cntS;
        m2 = plS;
        while (m2) { const int b = __ffs(m2) - 1; m2 &= m2 - 1; s_sep[oS++] = (u16)(tid * 8 + b); }
    }
    __syncthreads();
    const int total    = s_totalP;
    const int sepTotal = s_totalS;

    // --- constants & accumulators ---
    const u64 nxi2   = pack2(-pix, -pix);
    const u64 nyi2   = pack2(-piy, -piy);
    const u64 C2     = pack2( MAGIC,  MAGIC);
    const u64 nC2    = pack2(-MAGIC, -MAGIC);
    const u64 nOne2  = pack2(-1.0f, -1.0f);
    const u64 half2  = pack2(0.5f, 0.5f);
    const u64 sep2c  = pack2(SEP2F, SEP2F);
    const u64 perc2c = pack2(PERC2F, PERC2F);

    u64 Sx2 = 0, Sy2 = 0, Px2 = 0, Py2 = 0, Vx2 = 0, Vy2 = 0, Cn2 = 0;

    const ulonglong2* __restrict__ PV2 = (const ulonglong2*)g_pv;

    // --- main loop: segment sw of 32, 4-aligned boundaries, packed idx loads ---
    const int sw    = parity * NWARP + w;
    int k           = ((total * sw) >> 5) & ~3;
    const int kend4 = (sw == 31) ? (total & ~3) : (((total * (sw + 1)) >> 5) & ~3);

    for (; k < kend4; k += 4) {
        const uint2 pk = *(const uint2*)(s_pairs + k);
        const int i0 = pk.x & 0xffff;
        const int i1 = pk.x >> 16;
        const int i2 = pk.y & 0xffff;
        const int i3 = pk.y >> 16;
        const ulonglong2 pj0 = PV2[i0 * 2];
        const ulonglong2 vj0 = PV2[i0 * 2 + 1];
        const ulonglong2 pj1 = PV2[i1 * 2];
        const ulonglong2 vj1 = PV2[i1 * 2 + 1];
        const ulonglong2 pj2 = PV2[i2 * 2];
        const ulonglong2 vj2 = PV2[i2 * 2 + 1];
        const ulonglong2 pj3 = PV2[i3 * 2];
        const ulonglong2 vj3 = PV2[i3 * 2 + 1];
        PAIR_MAIN(pj0, vj0)
        PAIR_MAIN(pj1, vj1)
        PAIR_MAIN(pj2, vj2)
        PAIR_MAIN(pj3, vj3)
    }
    if (sw == 31) {
        for (k = total & ~3; k < total; ++k) {
            const int i0 = s_pairs[k];
            const ulonglong2 pj0 = PV2[i0 * 2];
            const ulonglong2 vj0 = PV2[i0 * 2 + 1];
            PAIR_MAIN(pj0, vj0)
        }
    }

    // --- separation side loop (tiny: sep radius = 0.02) ---
    for (int ks = sw; ks < sepTotal; ks += NSEG) {
        const int i0 = s_sep[ks];
        const ulonglong2 pj = PV2[i0 * 2];
        const u64 dx2 = f2add(pj.x, nxi2);
        const u64 rxp = f2add(f2add(dx2, C2), nC2);
        const u64 dwx = f2fma(rxp, nOne2, dx2);
        const u64 dy2 = f2add(pj.y, nyi2);
        const u64 ryp = f2add(f2add(dy2, C2), nC2);
        const u64 dwy = f2fma(ryp, nOne2, dy2);
        const u64 d2  = f2fma(dwy, dwy, f2mul(dwx, dwx));
        const u64 ms  = f2mask(f2fma(d2, nOne2, sep2c), half2);
        Sx2 = f2fma(dwx, ms, Sx2);
        Sy2 = f2fma(dwy, ms, Sy2);
    }

    // --- smem reduce (deterministic within block) ---
    float a, b;
    unpack2(Sx2, a, b);  red[w][lane][0] = a + b;
    unpack2(Sy2, a, b);  red[w][lane][1] = a + b;
    unpack2(Px2, a, b);  red[w][lane][2] = a + b;
    unpack2(Py2, a, b);  red[w][lane][3] = a + b;
    unpack2(Vx2, a, b);  red[w][lane][4] = a + b;
    unpack2(Vy2, a, b);  red[w][lane][5] = a + b;
    unpack2(Cn2, a, b);  red[w][lane][6] = a + b;
    __syncthreads();

    float s7[7];
    if (tid < 32) {
        #pragma unroll
        for (int comp = 0; comp < 7; ++comp) {
            float acc = 0.0f;
            #pragma unroll
            for (int sg = 0; sg < NWARP; ++sg) acc += red[sg][tid][comp];
            s7[comp] = acc;
            g_part[parity][comp][g * 32 + tid] = acc;
        }
        __threadfence();
    }
    __syncthreads();
    if (tid == 0) {
        const int old = atomicAdd(&g_ticket[g], 1);
        s_last = (old & 1);                    // 2 arrivals per run; parity selects last
    }
    __syncthreads();

    if (s_last && tid < 32) {
        __threadfence();
        // combine: part0 + part1 (fp add commutative -> same value either way)
        #pragma unroll
        for (int comp = 0; comp < 7; ++comp)
            s7[comp] += g_part[1 - parity][comp][g * 32 + tid];

        const float Sx = s7[0], Sy = s7[1], Px = s7[2], Py = s7[3];
        const float Vx = s7[4], Vy = s7[5];
        const float C  = s7[6] - 1.0f;         // remove self

        const int orig = g_orig[g * 32 + tid];
        const float2 vi = vel[orig];
        const float2 nz = noise[orig];

        float nrm = sqrtf(Sx * Sx + Sy * Sy);
        float inv = 1.0f / fmaxf(nrm, EPSF);
        const float sepx = -Sx * inv;
        const float sepy = -Sy * inv;

        const float invC = 1.0f / C;

        const float avx = (Vx - vi.x) * invC - vi.x;
        const float avy = (Vy - vi.y) * invC - vi.y;
        nrm = sqrtf(avx * avx + avy * avy);
        inv = 1.0f / fmaxf(nrm, EPSF);
        const float alix = avx * inv;
        const float aliy = avy * inv;

        const float cx2 = Px * invC;
        const float cy2 = Py * invC;
        nrm = sqrtf(cx2 * cx2 + cy2 * cy2);
        inv = 1.0f / fmaxf(nrm, EPSF);
        const float cohx = cx2 * inv;
        const float cohy = cy2 * inv;

        const float ws = *w_sep;
        const float wa = *w_ali;
        const float wc = *w_coh;
        const float wn = *w_ns;

        float ax = ws * sepx + wa * alix + wc * cohx + wn * nz.x;
        float ay = ws * sepy + wa * aliy + wc * cohy + wn * nz.y;

        nrm = sqrtf(ax * ax + ay * ay);
        if (nrm > 1.0f) {
            const float sc = 1.0f / fmaxf(nrm, EPSF);
            ax *= sc;
            ay *= sc;
        }

        out[orig] = make_float2(ax, ay);
    }
}

extern "C" void kernel_launch(void* const* d_in, const int* in_sizes, int n_in,
                              void* d_out, int out_size)
{
    const float2* pos   = (const float2*)d_in[0];
    const float2* vel   = (const float2*)d_in[1];
    const float2* noise = (const float2*)d_in[2];
    const float*  wsep  = (const float*)d_in[3];
    const float*  wali  = (const float*)d_in[4];
    const float*  wcoh  = (const float*)d_in[5];
    const float*  wns   = (const float*)d_in[6];
    float2* out = (float2*)d_out;

    kA_cells  <<<NBLKA, 256>>>(pos);
    kC_scatter<<<NBLKA, 256>>>(pos, vel);
    k1_main   <<<NTILE * 2, TPB1>>>(vel, noise, wsep, wali, wcoh, wns, out);
}

// round 13
// speedup vs baseline: 1.9005x; 1.0986x over previous
#include <cuda_runtime.h>

// BoidPolicy: all-pairs boids on a unit torus, N=8192, out acc [N,2] f32.
//
// Pipeline (graph-capturable, allocation-free, 3 launches):
//  kA: 16x16 snake cells + smem-atomic ranks + per-block histograms
//  kC: per-block redundant offset computation + scatter into interleaved records
//  k1: TWO blocks per 32-i tile (512 thr). Parity block p culls ONLY pairs with
//      (pair>>3)&1 == p (interleaved halves; no duplicated cull work), compacts
//      its own perception + separation lists, 16 warps take contiguous segments
//      (unroll-4, packed index loads), reduce, parity-ticketed fused epilogue.

#define NB      8192
#define NCELL   256
#define NBLKA   32
#define NTILE   256
#define TPB1    512
#define NWARP   16            // warps per block

#define SEP2F   4e-4f
#define PERC2F  0.04f
#define EPSF    1e-8f
#define MAGIC   12582912.0f   // 1.5 * 2^23
#define FULLM   0xffffffffu

typedef unsigned long long u64;
typedef unsigned short u16;

__device__ float4 g_pv[NB];             // pair p: [2p]=(xA,xB,yA,yB), [2p+1]=(vxA,vxB,vyA,vyB)
__device__ int    g_orig[NB];
__device__ int    g_cellid[NB];
__device__ int    g_lrank[NB];
__device__ int    g_cnt[NBLKA * NCELL];
__device__ float  g_part[2][7][NB];     // [parity][comp][sorted boid]
__device__ int    g_ticket[NTILE];      // +2 per run; parity selects last arrival

__device__ __forceinline__ u64 pack2(float lo, float hi) {
    u64 r; asm("mov.b64 %0,{%1,%2};" : "=l"(r) : "f"(lo), "f"(hi)); return r;
}
__device__ __forceinline__ void unpack2(u64 v, float& lo, float& hi) {
    asm("mov.b64 {%0,%1},%2;" : "=f"(lo), "=f"(hi) : "l"(v));
}
__device__ __forceinline__ u64 f2add(u64 a, u64 b) {
    u64 d; asm("add.rn.f32x2 %0,%1,%2;" : "=l"(d) : "l"(a), "l"(b)); return d;
}
__device__ __forceinline__ u64 f2mul(u64 a, u64 b) {
    u64 d; asm("mul.rn.f32x2 %0,%1,%2;" : "=l"(d) : "l"(a), "l"(b)); return d;
}
__device__ __forceinline__ u64 f2fma(u64 a, u64 b, u64 c) {
    u64 d; asm("fma.rn.f32x2 %0,%1,%2,%3;" : "=l"(d) : "l"(a), "l"(b), "l"(c)); return d;
}
// per-half: (t >= 0) ? 1.0f : 0.0f  (exact: copysign(0.5,t)+0.5)
__device__ __forceinline__ u64 f2mask(u64 t, u64 half2) {
    u64 s = (t & 0x8000000080000000ULL) | 0x3F0000003F000000ULL;
    return f2add(s, half2);
}
__device__ __forceinline__ float wrap1(float d) { return d - rintf(d); }
__device__ __forceinline__ float getX(const float* P, int idx) {
    return P[(idx >> 1) * 8 + (idx & 1)];
}
__device__ __forceinline__ float getY(const float* P, int idx) {
    return P[(idx >> 1) * 8 + 2 + (idx & 1)];
}

// ---------------- kA: cell ids + ranks + per-block histograms ----------------
__global__ void kA_cells(const float2* __restrict__ pos)
{
    __shared__ int hist[NCELL];
    const int tid = threadIdx.x;
    hist[tid] = 0;
    __syncthreads();

    const int e = blockIdx.x * 256 + tid;
    const float2 p = pos[e];
    int cx = (int)(p.x * 16.0f); cx = cx < 0 ? 0 : (cx > 15 ? 15 : cx);
    int cy = (int)(p.y * 16.0f); cy = cy < 0 ? 0 : (cy > 15 ? 15 : cy);
    const int lx   = (cy & 1) ? (15 - cx) : cx;       // snake order
    const int cell = (cy << 4) | lx;

    const int r = atomicAdd(&hist[cell], 1);
    g_cellid[e] = cell;
    g_lrank[e]  = r;
    __syncthreads();

    g_cnt[blockIdx.x * NCELL + tid] = hist[tid];
}

// ---------------- kC: per-block redundant offsets + scatter ----------------
__global__ void kC_scatter(const float2* __restrict__ pos,
                           const float2* __restrict__ vel)
{
    __shared__ int s_off[NCELL];
    __shared__ int wsum[8];
    __shared__ int wbase[8];

    const int tid  = threadIdx.x;      // doubles as cell index for the scan
    const int lane = tid & 31;
    const int w    = tid >> 5;
    const int b    = blockIdx.x;

    int tot = 0, part = 0;
    #pragma unroll
    for (int g = 0; g < NBLKA; ++g) {
        const int v = g_cnt[g * NCELL + tid];
        tot += v;
        if (g < b) part += v;
    }
    int s = tot;
    #pragma unroll
    for (int o = 1; o < 32; o <<= 1) {
        const int t = __shfl_up_sync(FULLM, s, o);
        if (lane >= o) s += t;
    }
    if (lane == 31) wsum[w] = s;
    __syncthreads();
    if (tid == 0) {
        int acc = 0;
        #pragma unroll
        for (int k = 0; k < 8; ++k) { wbase[k] = acc; acc += wsum[k]; }
    }
    __syncthreads();
    s_off[tid] = wbase[w] + s - tot + part;
    __syncthreads();

    const int e    = b * 256 + tid;
    const int cell = g_cellid[e];
    const int dst  = s_off[cell] + g_lrank[e];
    const float2 p = pos[e];
    const float2 v = vel[e];
    float* PV = (float*)g_pv;
    const int bb = (dst >> 1) * 8 + (dst & 1);
    PV[bb]     = p.x;
    PV[bb + 2] = p.y;
    PV[bb + 4] = v.x;
    PV[bb + 6] = v.y;
    g_orig[dst] = e;
}

// ---------------- k1: half-cull + compact + pair math + epilogue ----------------
#define PAIR_MAIN(PJ, VJ)                                                     \
    {                                                                         \
        const u64 dx2 = f2add((PJ).x, nxi2);                                  \
        const u64 rxp = f2add(f2add(dx2, C2), nC2);                           \
        const u64 dwx = f2fma(rxp, nOne2, dx2);                               \
        const u64 dy2 = f2add((PJ).y, nyi2);                                  \
        const u64 ryp = f2add(f2add(dy2, C2), nC2);                           \
        const u64 dwy = f2fma(ryp, nOne2, dy2);                               \
        const u64 d2  = f2fma(dwy, dwy, f2mul(dwx, dwx));                     \
        const u64 mp  = f2mask(f2fma(d2, nOne2, perc2c), half2);              \
        Px2 = f2fma(dwx, mp, Px2);                                            \
        Py2 = f2fma(dwy, mp, Py2);                                            \
        Vx2 = f2fma((VJ).x, mp, Vx2);                                         \
        Vy2 = f2fma((VJ).y, mp, Vy2);                                         \
        Cn2 = f2add(Cn2, mp);                                                 \
    }

__global__ __launch_bounds__(TPB1, 3)
void k1_main(const float2* __restrict__ vel,
             const float2* __restrict__ noise,
             const float*  __restrict__ w_sep,
             const float*  __restrict__ w_ali,
             const float*  __restrict__ w_coh,
             const float*  __restrict__ w_ns,
             float2*       __restrict__ out)
{
    __shared__ int      s_scanP[NWARP];
    __shared__ int      s_scanS[NWARP];
    __shared__ int      s_totalP, s_totalS, s_last;
    __shared__ __align__(8) u16 s_pairs[NB / 4];   // this block's half: 2048 max
    __shared__ u16      s_sep[NB / 4];
    __shared__ float    red[NWARP][32][8];

    const int tid    = threadIdx.x;
    const int lane   = tid & 31;
    const int w      = tid >> 5;
    const int g      = blockIdx.x >> 1;    // i-tile
    const int parity = blockIdx.x & 1;
    const int i      = g * 32 + lane;

    const float* P = (const float*)g_pv;
    const float pix = getX(P, i);
    const float piy = getY(P, i);

    // --- tile bbox (each warp computes an identical copy via shuffles) ---
    const float x0 = __shfl_sync(FULLM, pix, 0);
    const float y0 = __shfl_sync(FULLM, piy, 0);
    const float rx = wrap1(pix - x0);
    const float ry = wrap1(piy - y0);
    float mnx = rx, mxx = rx, mny = ry, mxy = ry;
    #pragma unroll
    for (int o = 16; o; o >>= 1) {
        mnx = fminf(mnx, __shfl_xor_sync(FULLM, mnx, o));
        mxx = fmaxf(mxx, __shfl_xor_sync(FULLM, mxx, o));
        mny = fminf(mny, __shfl_xor_sync(FULLM, mny, o));
        mxy = fmaxf(mxy, __shfl_xor_sync(FULLM, mxy, o));
    }
    const float bcx = x0 + 0.5f * (mnx + mxx);
    const float bcy = y0 + 0.5f * (mny + mxy);
    const float mrgx = 0.5f * (mxx - mnx) + 1e-5f;   // tile half-extent + slack
    const float mrgy = 0.5f * (mxy - mny) + 1e-5f;

    // --- pair-bbox liveness over THIS BLOCK'S interleaved half ---
    // m = tid*4 + q enumerates 2048 locals; p = (m>>3)<<4 | parity<<3 | (m&7).
    // Pair boids are snake-sort adjacent (no torus wrap) -> flat bbox exact.
    unsigned plP = 0, plS = 0;
    const int m0 = tid * 4;
    const int p0 = ((m0 >> 3) << 4) | (parity << 3) | (m0 & 7);
    #pragma unroll
    for (int q = 0; q < 4; ++q) {
        const float4 r4 = g_pv[(p0 + q) * 2];   // (xA, xB, yA, yB)
        const float pmnx = fminf(r4.x, r4.y), pmxx = fmaxf(r4.x, r4.y);
        const float pmny = fminf(r4.z, r4.w), pmxy = fmaxf(r4.z, r4.w);
        const float pcx = 0.5f * (pmnx + pmxx);
        const float phx = 0.5f * (pmxx - pmnx);
        const float pcy = 0.5f * (pmny + pmxy);
        const float phy = 0.5f * (pmxy - pmny);
        const float gx = fmaxf(0.0f, fabsf(wrap1(bcx - pcx)) - mrgx - phx);
        const float gy = fmaxf(0.0f, fabsf(wrap1(bcy - pcy)) - mrgy - phy);
        const float gap2 = gx * gx + gy * gy;
        plP |= (gap2 <= PERC2F ? 1u : 0u) << q;
        plS |= (gap2 <= SEP2F  ? 1u : 0u) << q;
    }

    const int cntP = __popc(plP);
    const int cntS = __popc(plS);
    int sP = cntP, sS = cntS;
    #pragma unroll
    for (int o = 1; o < 32; o <<= 1) {
        const int tP = __shfl_up_sync(FULLM, sP, o);
        const int tS = __shfl_up_sync(FULLM, sS, o);
        if (lane >= o) { sP += tP; sS += tS; }
    }
    if (lane == 31) { s_scanP[w] = sP; s_scanS[w] = sS; }
    __syncthreads();
    if (tid == 0) {
        int aP = 0, aS = 0;
        #pragma unroll
        for (int k = 0; k < NWARP; ++k) {
            const int vP = s_scanP[k]; s_scanP[k] = aP; aP += vP;
            const int vS = s_scanS[k]; s_scanS[k] = aS; aS += vS;
        }
        s_totalP = aP; s_totalS = aS;
    }
    __syncthreads();
    {
        int oP = s_scanP[w] + sP - cntP;
        unsigned m2 = plP;
        while (m2) { const int b = __ffs(m2) - 1; m2 &= m2 - 1; s_pairs[oP++] = (u16)(p0 + b); }
        int oS = s_scanS[w] + sS - cntS;
        m2 = plS;
        while (m2) { const int b = __ffs(m2) - 1; m2 &= m2 - 1; s_sep[oS++] = (u16)(p0 + b); }
    }
    __syncthreads();
    const int total    = s_totalP;
    const int sepTotal = s_totalS;

    // --- constants & accumulators ---
    const u64 nxi2   = pack2(-pix, -pix);
    const u64 nyi2   = pack2(-piy, -piy);
    const u64 C2     = pack2( MAGIC,  MAGIC);
    const u64 nC2    = pack2(-MAGIC, -MAGIC);
    const u64 nOne2  = pack2(-1.0f, -1.0f);
    const u64 half2  = pack2(0.5f, 0.5f);
    const u64 sep2c  = pack2(SEP2F, SEP2F);
    const u64 perc2c = pack2(PERC2F, PERC2F);

    u64 Sx2 = 0, Sy2 = 0, Px2 = 0, Py2 = 0, Vx2 = 0, Vy2 = 0, Cn2 = 0;

    const ulonglong2* __restrict__ PV2 = (const ulonglong2*)g_pv;

    // --- main loop: warp w takes contiguous segment of this block's list ---
    int k           = ((total * w) >> 4) & ~3;      // NWARP = 16
    const int kend4 = (w == 15) ? (total & ~3) : (((total * (w + 1)) >> 4) & ~3);

    for (; k < kend4; k += 4) {
        const uint2 pk = *(const uint2*)(s_pairs + k);
        const int i0 = pk.x & 0xffff;
        const int i1 = pk.x >> 16;
        const int i2 = pk.y & 0xffff;
        const int i3 = pk.y >> 16;
        const ulonglong2 pj0 = PV2[i0 * 2];
        const ulonglong2 vj0 = PV2[i0 * 2 + 1];
        const ulonglong2 pj1 = PV2[i1 * 2];
        const ulonglong2 vj1 = PV2[i1 * 2 + 1];
        const ulonglong2 pj2 = PV2[i2 * 2];
        const ulonglong2 vj2 = PV2[i2 * 2 + 1];
        const ulonglong2 pj3 = PV2[i3 * 2];
        const ulonglong2 vj3 = PV2[i3 * 2 + 1];
        PAIR_MAIN(pj0, vj0)
        PAIR_MAIN(pj1, vj1)
        PAIR_MAIN(pj2, vj2)
        PAIR_MAIN(pj3, vj3)
    }
    if (w == 15) {
        for (k = total & ~3; k < total; ++k) {
            const int i0 = s_pairs[k];
            const ulonglong2 pj0 = PV2[i0 * 2];
            const ulonglong2 vj0 = PV2[i0 * 2 + 1];
            PAIR_MAIN(pj0, vj0)
        }
    }

    // --- separation side loop (tiny: sep radius = 0.02) ---
    for (int ks = w; ks < sepTotal; ks += NWARP) {
        const int i0 = s_sep[ks];
        const ulonglong2 pj = PV2[i0 * 2];
        const u64 dx2 = f2add(pj.x, nxi2);
        const u64 rxp = f2add(f2add(dx2, C2), nC2);
        const u64 dwx = f2fma(rxp, nOne2, dx2);
        const u64 dy2 = f2add(pj.y, nyi2);
        const u64 ryp = f2add(f2add(dy2, C2), nC2);
        const u64 dwy = f2fma(ryp, nOne2, dy2);
        const u64 d2  = f2fma(dwy, dwy, f2mul(dwx, dwx));
        const u64 ms  = f2mask(f2fma(d2, nOne2, sep2c), half2);
        Sx2 = f2fma(dwx, ms, Sx2);
        Sy2 = f2fma(dwy, ms, Sy2);
    }

    // --- smem reduce (deterministic within block) ---
    float a, b;
    unpack2(Sx2, a, b);  red[w][lane][0] = a + b;
    unpack2(Sy2, a, b);  red[w][lane][1] = a + b;
    unpack2(Px2, a, b);  red[w][lane][2] = a + b;
    unpack2(Py2, a, b);  red[w][lane][3] = a + b;
    unpack2(Vx2, a, b);  red[w][lane][4] = a + b;
    unpack2(Vy2, a, b);  red[w][lane][5] = a + b;
    unpack2(Cn2, a, b);  red[w][lane][6] = a + b;
    __syncthreads();

    float s7[7];
    if (tid < 32) {
        #pragma unroll
        for (int comp = 0; comp < 7; ++comp) {
            float acc = 0.0f;
            #pragma unroll
            for (int sg = 0; sg < NWARP; ++sg) acc += red[sg][tid][comp];
            s7[comp] = acc;
            g_part[parity][comp][g * 32 + tid] = acc;
        }
        __threadfence();
    }
    __syncthreads();
    if (tid == 0) {
        const int old = atomicAdd(&g_ticket[g], 1);
        s_last = (old & 1);                    // 2 arrivals per run; parity selects last
    }
    __syncthreads();

    if (s_last && tid < 32) {
        __threadfence();
        // combine: part0 + part1 (fp add commutative -> same value either way)
        #pragma unroll
        for (int comp = 0; comp < 7; ++comp)
            s7[comp] += g_part[1 - parity][comp][g * 32 + tid];

        const float Sx = s7[0], Sy = s7[1], Px = s7[2], Py = s7[3];
        const float Vx = s7[4], Vy = s7[5];
        const float C  = s7[6] - 1.0f;         // remove self

        const int orig = g_orig[g * 32 + tid];
        const float2 vi = vel[orig];
        const float2 nz = noise[orig];

        float nrm = sqrtf(Sx * Sx + Sy * Sy);
        float inv = 1.0f / fmaxf(nrm, EPSF);
        const float sepx = -Sx * inv;
        const float sepy = -Sy * inv;

        const float invC = 1.0f / C;

        const float avx = (Vx - vi.x) * invC - vi.x;
        const float avy = (Vy - vi.y) * invC - vi.y;
        nrm = sqrtf(avx * avx + avy * avy);
        inv = 1.0f / fmaxf(nrm, EPSF);
        const float alix = avx * inv;
        const float aliy = avy * inv;

        const float cx2 = Px * invC;
        const float cy2 = Py * invC;
        nrm = sqrtf(cx2 * cx2 + cy2 * cy2);
        inv = 1.0f / fmaxf(nrm, EPSF);
        const float cohx = cx2 * inv;
        const float cohy = cy2 * inv;

        const float ws = *w_sep;
        const float wa = *w_ali;
        const float wc = *w_coh;
        const float wn = *w_ns;

        float ax = ws * sepx + wa * alix + wc * cohx + wn * nz.x;
        float ay = ws * sepy + wa * aliy + wc * cohy + wn * nz.y;

        nrm = sqrtf(ax * ax + ay * ay);
        if (nrm > 1.0f) {
            const float sc = 1.0f / fmaxf(nrm, EPSF);
            ax *= sc;
            ay *= sc;
        }

        out[orig] = make_float2(ax, ay);
    }
}

extern "C" void kernel_launch(void* const* d_in, const int* in_sizes, int n_in,
                              void* d_out, int out_size)
{
    const float2* pos   = (const float2*)d_in[0];
    const float2* vel   = (const float2*)d_in[1];
    const float2* noise = (const float2*)d_in[2];
    const float*  wsep  = (const float*)d_in[3];
    const float*  wali  = (const float*)d_in[4];
    const float*  wcoh  = (const float*)d_in[5];
    const float*  wns   = (const float*)d_in[6];
    float2* out = (float2*)d_out;

    kA_cells  <<<NBLKA, 256>>>(pos);
    kC_scatter<<<NBLKA, 256>>>(pos, vel);
    k1_main   <<<NTILE * 2, TPB1>>>(vel, noise, wsep, wali, wcoh, wns, out);
}